// round 1
// baseline (speedup 1.0000x reference)
#include <cuda_runtime.h>
#include <math.h>

// Problem constants: B=2, L=2048, D=1024, N=16
#define M_ROWS 4096      // B*L
#define K_DIM  1024      // D
#define DN     16384     // D*N

// Scratch: intermediate GEMM outputs (allowed: __device__ globals, no alloc)
__device__ float g_dt[(size_t)M_ROWS * 1024];   //  16 MB
__device__ float g_Bt[(size_t)M_ROWS * DN];     // 256 MB
__device__ float g_Ct[(size_t)M_ROWS * DN];     // 256 MB

// ---------------------------------------------------------------------------
// GEMM: out[m, o] = sum_k A[m,k] * W[o,k] + bias[o]   (A: M x K, W: N x K)
// BM=128, BN=128, BK=16, 256 threads, 8x8 microtile.
// SOFTPLUS epilogue adds bias2 and applies softplus (for dt path).
// which: 0 -> g_dt, 1 -> g_Bt, 2 -> g_Ct
// ---------------------------------------------------------------------------
template <bool SOFTPLUS>
__global__ __launch_bounds__(256, 2)
void gemm_epi_kernel(const float* __restrict__ A,
                     const float* __restrict__ W,
                     const float* __restrict__ bias,
                     const float* __restrict__ bias2,
                     int Ncols, int which)
{
    constexpr int BM = 128, BN = 128, BK = 16;
    __shared__ float As[BK][BM];
    __shared__ float Bs[BK][BN];

    float* out = (which == 0) ? g_dt : (which == 1) ? g_Bt : g_Ct;

    const int tid   = threadIdx.x;          // 0..255
    const int mBase = blockIdx.y * BM;
    const int nBase = blockIdx.x * BN;

    const int lr = tid >> 2;                // 0..63  (load row)
    const int lc = (tid & 3) << 2;          // 0,4,8,12 (load col, float4)
    const int tr = tid >> 4;                // 0..15  (thread tile row)
    const int tc = tid & 15;                // 0..15  (thread tile col)

    float acc[8][8];
    #pragma unroll
    for (int i = 0; i < 8; i++)
        #pragma unroll
        for (int j = 0; j < 8; j++)
            acc[i][j] = 0.0f;

    const float* Ap0 = A + (size_t)(mBase + lr)      * K_DIM + lc;
    const float* Ap1 = A + (size_t)(mBase + lr + 64) * K_DIM + lc;
    const float* Wp0 = W + (size_t)(nBase + lr)      * K_DIM + lc;
    const float* Wp1 = W + (size_t)(nBase + lr + 64) * K_DIM + lc;

    for (int k0 = 0; k0 < K_DIM; k0 += BK) {
        float4 a0 = *(const float4*)(Ap0 + k0);
        float4 a1 = *(const float4*)(Ap1 + k0);
        float4 b0 = *(const float4*)(Wp0 + k0);
        float4 b1 = *(const float4*)(Wp1 + k0);

        __syncthreads();   // previous iteration's compute done before overwrite

        As[lc + 0][lr]      = a0.x; As[lc + 1][lr]      = a0.y;
        As[lc + 2][lr]      = a0.z; As[lc + 3][lr]      = a0.w;
        As[lc + 0][lr + 64] = a1.x; As[lc + 1][lr + 64] = a1.y;
        As[lc + 2][lr + 64] = a1.z; As[lc + 3][lr + 64] = a1.w;
        Bs[lc + 0][lr]      = b0.x; Bs[lc + 1][lr]      = b0.y;
        Bs[lc + 2][lr]      = b0.z; Bs[lc + 3][lr]      = b0.w;
        Bs[lc + 0][lr + 64] = b1.x; Bs[lc + 1][lr + 64] = b1.y;
        Bs[lc + 2][lr + 64] = b1.z; Bs[lc + 3][lr + 64] = b1.w;

        __syncthreads();

        #pragma unroll
        for (int kk = 0; kk < BK; kk++) {
            float ar[8], br[8];
            *(float4*)&ar[0] = *(const float4*)&As[kk][tr * 8];
            *(float4*)&ar[4] = *(const float4*)&As[kk][tr * 8 + 4];
            *(float4*)&br[0] = *(const float4*)&Bs[kk][tc * 8];
            *(float4*)&br[4] = *(const float4*)&Bs[kk][tc * 8 + 4];
            #pragma unroll
            for (int i = 0; i < 8; i++)
                #pragma unroll
                for (int j = 0; j < 8; j++)
                    acc[i][j] = fmaf(ar[i], br[j], acc[i][j]);
        }
    }

    // Epilogue
    #pragma unroll
    for (int i = 0; i < 8; i++) {
        const int row  = mBase + tr * 8 + i;
        const int col0 = nBase + tc * 8;
        float v[8];
        #pragma unroll
        for (int j = 0; j < 8; j++) {
            float t = acc[i][j] + bias[col0 + j];
            if (SOFTPLUS) {
                t += bias2[col0 + j];
                // numerically stable softplus, matches jax.nn.softplus
                t = fmaxf(t, 0.0f) + log1pf(__expf(-fabsf(t)));
            }
            v[j] = t;
        }
        float* o = out + (size_t)row * Ncols + col0;
        *(float4*)(o)     = make_float4(v[0], v[1], v[2], v[3]);
        *(float4*)(o + 4) = make_float4(v[4], v[5], v[6], v[7]);
    }
}

// ---------------------------------------------------------------------------
// Scan: one thread per (b, d, n). Block = 16 d-channels x 16 n = 256 threads.
// Grid = B * D/16 = 128 blocks.
// Discretization (A_bar, B_bar, x_in) computed on the fly.
// Reduction over n via half-warp shuffles (width 16).
// ---------------------------------------------------------------------------
__global__ __launch_bounds__(256)
void scan_kernel(const float* __restrict__ u,
                 const float* __restrict__ logA,
                 const float* __restrict__ Dskip,
                 float* __restrict__ y)
{
    const int tid  = threadIdx.x;
    const int n    = tid & 15;
    const int dl   = tid >> 4;              // 0..15
    const int blk  = blockIdx.x;            // 0..127
    const int b    = blk >> 6;              // 64 blocks per batch
    const int dblk = blk & 63;
    const int d    = dblk * 16 + dl;

    const float Aval = -__expf(logA[d * 16 + n]);  // A < 0
    const float invA = 1.0f / Aval;
    const float dsk  = Dskip[d];

    const float* uB  = u    + (size_t)b * 2048 * 1024;
    const float* dtB = g_dt + (size_t)b * 2048 * 1024;
    const float* BtB = g_Bt + (size_t)b * 2048 * DN;
    const float* CtB = g_Ct + (size_t)b * 2048 * DN;
    float*       yB  = y    + (size_t)b * 2048 * 1024;

    const int off256 = dblk * 256 + tid;    // (d*16 + n) within a DN row

    float h = 0.0f;

    #pragma unroll 2
    for (int t = 0; t < 2048; ++t) {
        const float uv  = uB [t * 1024 + d];
        const float dtv = dtB[t * 1024 + d];
        const float Btv = BtB[(size_t)t * DN + off256];
        const float Ctv = CtB[(size_t)t * DN + off256];

        const float a = __expf(dtv * Aval);           // A_bar
        const float x = (a - 1.0f) * invA * Btv * uv; // B_bar * u
        h = fmaf(a, h, x);

        float p = Ctv * h;
        p += __shfl_down_sync(0xffffffffu, p, 8, 16);
        p += __shfl_down_sync(0xffffffffu, p, 4, 16);
        p += __shfl_down_sync(0xffffffffu, p, 2, 16);
        p += __shfl_down_sync(0xffffffffu, p, 1, 16);

        if (n == 0)
            yB[t * 1024 + d] = p + dsk * uv;
    }
}

// ---------------------------------------------------------------------------
extern "C" void kernel_launch(void* const* d_in, const int* in_sizes, int n_in,
                              void* d_out, int out_size)
{
    const float* u       = (const float*)d_in[0];
    const float* log_A   = (const float*)d_in[1];
    const float* D_skip  = (const float*)d_in[2];
    const float* dt_bias = (const float*)d_in[3];
    const float* W_dt    = (const float*)d_in[4];
    const float* b_dt    = (const float*)d_in[5];
    const float* W_B     = (const float*)d_in[6];
    const float* b_B     = (const float*)d_in[7];
    const float* W_C     = (const float*)d_in[8];
    const float* b_C     = (const float*)d_in[9];
    float* y = (float*)d_out;

    // dt = softplus(u @ W_dt^T + b_dt + dt_bias)
    gemm_epi_kernel<true ><<<dim3(1024 / 128, M_ROWS / 128), 256>>>(
        u, W_dt, b_dt, dt_bias, 1024, 0);
    // Bt = u @ W_B^T + b_B
    gemm_epi_kernel<false><<<dim3(DN / 128, M_ROWS / 128), 256>>>(
        u, W_B, b_B, nullptr, DN, 1);
    // Ct = u @ W_C^T + b_C
    gemm_epi_kernel<false><<<dim3(DN / 128, M_ROWS / 128), 256>>>(
        u, W_C, b_C, nullptr, DN, 2);

    // fused discretization + recurrent scan + skip connection
    scan_kernel<<<128, 256>>>(u, log_A, D_skip, y);
}

// round 4
// speedup vs baseline: 3.1310x; 3.1310x over previous
#include <cuda_runtime.h>
#include <cuda_bf16.h>
#include <math.h>
#include <stdint.h>

// Problem constants: B=2, L=2048, D=1024, N=16
#define M_ROWS 4096
#define K_DIM  1024
#define DN     16384

// ---------------------------------------------------------------------------
// Device scratch (no allocs allowed -> __device__ globals)
// ---------------------------------------------------------------------------
__device__ __align__(256) __nv_bfloat16 g_u_hi [(size_t)M_ROWS * K_DIM];
__device__ __align__(256) __nv_bfloat16 g_u_lo [(size_t)M_ROWS * K_DIM];
__device__ __align__(256) __nv_bfloat16 g_Wdt_hi[(size_t)1024  * K_DIM];
__device__ __align__(256) __nv_bfloat16 g_Wdt_lo[(size_t)1024  * K_DIM];
__device__ __align__(256) __nv_bfloat16 g_WB_hi [(size_t)DN    * K_DIM];
__device__ __align__(256) __nv_bfloat16 g_WB_lo [(size_t)DN    * K_DIM];
__device__ __align__(256) __nv_bfloat16 g_WC_hi [(size_t)DN    * K_DIM];
__device__ __align__(256) __nv_bfloat16 g_WC_lo [(size_t)DN    * K_DIM];
__device__ __align__(256) float g_dt[(size_t)M_ROWS * 1024];
__device__ __align__(256) float g_Bt[(size_t)M_ROWS * DN];
__device__ __align__(256) float g_Ct[(size_t)M_ROWS * DN];

// ---------------------------------------------------------------------------
// Helpers (family-portable PTX only: cp.async, ldmatrix, mma.sync)
// ---------------------------------------------------------------------------
__device__ __forceinline__ uint32_t smem_u32(const void* p) {
    uint32_t a;
    asm("{ .reg .u64 t; cvta.to.shared.u64 t, %1; cvt.u32.u64 %0, t; }"
        : "=r"(a) : "l"(p));
    return a;
}
__device__ __forceinline__ void cp16(uint32_t s, const void* g) {
    asm volatile("cp.async.cg.shared.global [%0], [%1], 16;" :: "r"(s), "l"(g));
}
#define CP_COMMIT() asm volatile("cp.async.commit_group;" ::: "memory")
#define CP_WAIT1()  asm volatile("cp.async.wait_group 1;"  ::: "memory")
#define CP_WAIT0()  asm volatile("cp.async.wait_group 0;"  ::: "memory")

__device__ __forceinline__ void ldsm4(uint32_t* r, uint32_t addr) {
    asm volatile("ldmatrix.sync.aligned.m8n8.x4.shared.b16 {%0,%1,%2,%3}, [%4];"
                 : "=r"(r[0]), "=r"(r[1]), "=r"(r[2]), "=r"(r[3]) : "r"(addr));
}
__device__ __forceinline__ void mma16816(float* d, const uint32_t* a, const uint32_t* b) {
    asm volatile(
        "mma.sync.aligned.m16n8k16.row.col.f32.bf16.bf16.f32 "
        "{%0,%1,%2,%3}, {%4,%5,%6,%7}, {%8,%9}, {%0,%1,%2,%3};"
        : "+f"(d[0]), "+f"(d[1]), "+f"(d[2]), "+f"(d[3])
        : "r"(a[0]), "r"(a[1]), "r"(a[2]), "r"(a[3]), "r"(b[0]), "r"(b[1]));
}

// ---------------------------------------------------------------------------
// Split fp32 -> (bf16 hi, bf16 lo). which: 0=u, 1=W_dt, 2=W_B, 3=W_C
// ---------------------------------------------------------------------------
__global__ __launch_bounds__(256)
void split_kernel(const float* __restrict__ src, int which, int n4)
{
    __nv_bfloat16 *hi, *lo;
    switch (which) {
        case 0:  hi = g_u_hi;   lo = g_u_lo;   break;
        case 1:  hi = g_Wdt_hi; lo = g_Wdt_lo; break;
        case 2:  hi = g_WB_hi;  lo = g_WB_lo;  break;
        default: hi = g_WC_hi;  lo = g_WC_lo;  break;
    }
    int i = blockIdx.x * 256 + threadIdx.x;
    if (i >= n4) return;
    float4 x = ((const float4*)src)[i];
    __nv_bfloat16 h[4], l[4];
    float xs[4] = {x.x, x.y, x.z, x.w};
    #pragma unroll
    for (int j = 0; j < 4; j++) {
        h[j] = __float2bfloat16(xs[j]);
        l[j] = __float2bfloat16(xs[j] - __bfloat162float(h[j]));
    }
    *((uint2*)(hi + 4 * (size_t)i)) = *(uint2*)h;
    *((uint2*)(lo + 4 * (size_t)i)) = *(uint2*)l;
}

// ---------------------------------------------------------------------------
// bf16 mma.sync GEMM, 3-term split: out = A*W^T + bias
//   Block 128x256, 8 warps (2x4), warp tile 64x64, K-chunk 32, double buffer.
//   smem rows padded to 40 bf16 (80B) -> conflict-free ldmatrix.
// which: 0 -> Wdt -> g_dt (softplus); 1 -> WB -> g_Bt; 2 -> WC -> g_Ct
// ---------------------------------------------------------------------------
#define PAD_ROW   40          // bf16 elems per smem row (32 data + 8 pad)
#define ROW_B     80          // bytes per smem row
#define A_HI_OFF  0
#define A_LO_OFF  10240       // 128*80
#define B_HI_OFF  20480
#define B_LO_OFF  40960       // +256*80
#define STAGE_SZ  61440
#define SMEM_GEMM (2 * STAGE_SZ)

template <bool SOFTPLUS>
__global__ __launch_bounds__(256, 1)
void gemm_mma(int which, const float* __restrict__ bias1,
              const float* __restrict__ bias2, int Ncols)
{
    extern __shared__ char smem[];
    const uint32_t sb = smem_u32(smem);
    const int tid = threadIdx.x;
    const int wid = tid >> 5;
    const int lane = tid & 31;
    const int mBase = blockIdx.x * 128;
    const int nBase = blockIdx.y * 256;
    const int warp_m = (wid >> 2) * 64;   // 0 or 64
    const int warp_n = (wid & 3) * 64;    // 0,64,128,192

    const __nv_bfloat16* Ah = g_u_hi;
    const __nv_bfloat16* Al = g_u_lo;
    const __nv_bfloat16 *Bh, *Bl;
    float* out;
    if (which == 0)      { Bh = g_Wdt_hi; Bl = g_Wdt_lo; out = g_dt; }
    else if (which == 1) { Bh = g_WB_hi;  Bl = g_WB_lo;  out = g_Bt; }
    else                 { Bh = g_WC_hi;  Bl = g_WC_lo;  out = g_Ct; }

    // ---- stage loader: A[128x32] hi/lo + B[256x32] hi/lo
    auto load_stage = [&](int s, int k0) {
        const uint32_t st = sb + (uint32_t)s * STAGE_SZ;
        #pragma unroll
        for (int i = 0; i < 2; i++) {                 // A: 512 cp16 per buf
            int idx = i * 256 + tid;
            int row = idx >> 2, c = idx & 3;
            uint32_t so = (uint32_t)(row * ROW_B + c * 16);
            size_t go = (size_t)(mBase + row) * K_DIM + k0 + c * 8;
            cp16(st + A_HI_OFF + so, Ah + go);
            cp16(st + A_LO_OFF + so, Al + go);
        }
        #pragma unroll
        for (int i = 0; i < 4; i++) {                 // B: 1024 cp16 per buf
            int idx = i * 256 + tid;
            int row = idx >> 2, c = idx & 3;
            uint32_t so = (uint32_t)(row * ROW_B + c * 16);
            size_t go = (size_t)(nBase + row) * K_DIM + k0 + c * 8;
            cp16(st + B_HI_OFF + so, Bh + go);
            cp16(st + B_LO_OFF + so, Bl + go);
        }
    };

    float acc[4][8][4];
    #pragma unroll
    for (int i = 0; i < 4; i++)
        #pragma unroll
        for (int j = 0; j < 8; j++)
            #pragma unroll
            for (int q = 0; q < 4; q++)
                acc[i][j][q] = 0.0f;

    // ldmatrix per-lane address components
    const int aRow  = lane & 15;          // A: row within 16x16 tile
    const int aHalf = lane >> 4;          // A: k half (0/1) -> +16B
    const int bJ    = lane & 7;           // B: row within 8
    const int bG    = lane >> 3;          // B: group 0..3
    const int bRow  = (bG >> 1) * 8 + bJ; // n row within 16
    const int bHalf = bG & 1;             // k half

    load_stage(0, 0);  CP_COMMIT();
    load_stage(1, 32); CP_COMMIT();

    const int NCHUNK = K_DIM / 32;        // 32
    for (int c = 0; c < NCHUNK; c++) {
        const uint32_t st = sb + (uint32_t)(c & 1) * STAGE_SZ;
        CP_WAIT1();
        __syncthreads();

        #pragma unroll
        for (int ks = 0; ks < 2; ks++) {
            const uint32_t kOff = ks * 32;  // 16 bf16 = 32B
            uint32_t ah[4][4], al[4][4], bh[8][2], bl[8][2];
            #pragma unroll
            for (int i = 0; i < 4; i++) {
                uint32_t ao = (uint32_t)((warp_m + i * 16 + aRow) * ROW_B)
                              + kOff + aHalf * 16;
                ldsm4(ah[i], st + A_HI_OFF + ao);
                ldsm4(al[i], st + A_LO_OFF + ao);
            }
            #pragma unroll
            for (int j = 0; j < 4; j++) {
                uint32_t bo = (uint32_t)((warp_n + j * 16 + bRow) * ROW_B)
                              + kOff + bHalf * 16;
                uint32_t rh[4], rl[4];
                ldsm4(rh, st + B_HI_OFF + bo);
                ldsm4(rl, st + B_LO_OFF + bo);
                bh[2*j][0] = rh[0]; bh[2*j][1] = rh[1];
                bh[2*j+1][0] = rh[2]; bh[2*j+1][1] = rh[3];
                bl[2*j][0] = rl[0]; bl[2*j][1] = rl[1];
                bl[2*j+1][0] = rl[2]; bl[2*j+1][1] = rl[3];
            }
            #pragma unroll
            for (int i = 0; i < 4; i++)
                #pragma unroll
                for (int j = 0; j < 8; j++) {
                    mma16816(acc[i][j], ah[i], bh[j]);
                    mma16816(acc[i][j], ah[i], bl[j]);
                    mma16816(acc[i][j], al[i], bh[j]);
                }
        }

        __syncthreads();   // all warps done reading stage before refill
        if (c + 2 < NCHUNK) { load_stage(c & 1, (c + 2) * 32); }
        CP_COMMIT();       // keep group accounting uniform
    }
    CP_WAIT0();

    // ---- epilogue: registers -> global, +bias (and softplus for dt)
    const int r0   = (lane >> 2);         // 0..7
    const int c0   = (lane & 3) * 2;      // 0,2,4,6
    #pragma unroll
    for (int i = 0; i < 4; i++) {
        const int gr0 = mBase + warp_m + i * 16 + r0;
        #pragma unroll
        for (int j = 0; j < 8; j++) {
            const int gc = nBase + warp_n + j * 8 + c0;
            float v0 = acc[i][j][0] + bias1[gc];
            float v1 = acc[i][j][1] + bias1[gc + 1];
            float v2 = acc[i][j][2] + bias1[gc];
            float v3 = acc[i][j][3] + bias1[gc + 1];
            if (SOFTPLUS) {
                v0 += bias2[gc];     v1 += bias2[gc + 1];
                v2 += bias2[gc];     v3 += bias2[gc + 1];
                v0 = fmaxf(v0, 0.0f) + log1pf(__expf(-fabsf(v0)));
                v1 = fmaxf(v1, 0.0f) + log1pf(__expf(-fabsf(v1)));
                v2 = fmaxf(v2, 0.0f) + log1pf(__expf(-fabsf(v2)));
                v3 = fmaxf(v3, 0.0f) + log1pf(__expf(-fabsf(v3)));
            }
            *(float2*)(out + (size_t)gr0       * Ncols + gc) = make_float2(v0, v1);
            *(float2*)(out + (size_t)(gr0 + 8) * Ncols + gc) = make_float2(v2, v3);
        }
    }
}

// ---------------------------------------------------------------------------
// Scan: one thread per (b, d, n). Block = 16 d x 16 n. Grid = 128.
// ---------------------------------------------------------------------------
__global__ __launch_bounds__(256)
void scan_kernel(const float* __restrict__ u,
                 const float* __restrict__ logA,
                 const float* __restrict__ Dskip,
                 float* __restrict__ y)
{
    const int tid  = threadIdx.x;
    const int n    = tid & 15;
    const int dl   = tid >> 4;
    const int blk  = blockIdx.x;
    const int b    = blk >> 6;
    const int dblk = blk & 63;
    const int d    = dblk * 16 + dl;

    const float Aval = -__expf(logA[d * 16 + n]);
    const float invA = 1.0f / Aval;
    const float dsk  = Dskip[d];

    const float* uB  = u    + (size_t)b * 2048 * 1024;
    const float* dtB = g_dt + (size_t)b * 2048 * 1024;
    const float* BtB = g_Bt + (size_t)b * 2048 * DN;
    const float* CtB = g_Ct + (size_t)b * 2048 * DN;
    float*       yB  = y    + (size_t)b * 2048 * 1024;

    const int off256 = dblk * 256 + tid;

    float h = 0.0f;
    #pragma unroll 2
    for (int t = 0; t < 2048; ++t) {
        const float uv  = uB [t * 1024 + d];
        const float dtv = dtB[t * 1024 + d];
        const float Btv = BtB[(size_t)t * DN + off256];
        const float Ctv = CtB[(size_t)t * DN + off256];

        const float a = __expf(dtv * Aval);
        const float x = (a - 1.0f) * invA * Btv * uv;
        h = fmaf(a, h, x);

        float p = Ctv * h;
        p += __shfl_down_sync(0xffffffffu, p, 8, 16);
        p += __shfl_down_sync(0xffffffffu, p, 4, 16);
        p += __shfl_down_sync(0xffffffffu, p, 2, 16);
        p += __shfl_down_sync(0xffffffffu, p, 1, 16);

        if (n == 0)
            yB[t * 1024 + d] = p + dsk * uv;
    }
}

// ---------------------------------------------------------------------------
extern "C" void kernel_launch(void* const* d_in, const int* in_sizes, int n_in,
                              void* d_out, int out_size)
{
    const float* u       = (const float*)d_in[0];
    const float* log_A   = (const float*)d_in[1];
    const float* D_skip  = (const float*)d_in[2];
    const float* dt_bias = (const float*)d_in[3];
    const float* W_dt    = (const float*)d_in[4];
    const float* b_dt    = (const float*)d_in[5];
    const float* W_B     = (const float*)d_in[6];
    const float* b_B     = (const float*)d_in[7];
    const float* W_C     = (const float*)d_in[8];
    const float* b_C     = (const float*)d_in[9];
    float* y = (float*)d_out;

    cudaFuncSetAttribute(gemm_mma<false>, cudaFuncAttributeMaxDynamicSharedMemorySize, SMEM_GEMM);
    cudaFuncSetAttribute(gemm_mma<true>,  cudaFuncAttributeMaxDynamicSharedMemorySize, SMEM_GEMM);

    // fp32 -> bf16 hi/lo splits
    split_kernel<<<(M_ROWS * K_DIM / 4) / 256, 256>>>(u,    0, M_ROWS * K_DIM / 4);
    split_kernel<<<(1024 * K_DIM   / 4) / 256, 256>>>(W_dt, 1, 1024 * K_DIM / 4);
    split_kernel<<<(DN * K_DIM     / 4) / 256, 256>>>(W_B,  2, DN * K_DIM / 4);
    split_kernel<<<(DN * K_DIM     / 4) / 256, 256>>>(W_C,  3, DN * K_DIM / 4);

    // tensor-core GEMMs (legacy mma.sync path; grid.x = M fastest for L2 reuse)
    gemm_mma<true ><<<dim3(32, 4),  256, SMEM_GEMM>>>(0, b_dt, dt_bias, 1024);
    gemm_mma<false><<<dim3(32, 64), 256, SMEM_GEMM>>>(1, b_B,  nullptr, DN);
    gemm_mma<false><<<dim3(32, 64), 256, SMEM_GEMM>>>(2, b_C,  nullptr, DN);

    // fused discretization + recurrent scan + skip
    scan_kernel<<<128, 256>>>(u, log_A, D_skip, y);
}

// round 5
// speedup vs baseline: 3.9440x; 1.2597x over previous
#include <cuda_runtime.h>
#include <cuda_fp16.h>
#include <math.h>
#include <stdint.h>

// Problem constants: B=2, L=2048, D=1024, N=16
#define M_ROWS 4096
#define K_DIM  1024
#define DN     16384

// ---------------------------------------------------------------------------
// Device scratch (no allocs allowed -> __device__ globals)
// ---------------------------------------------------------------------------
__device__ __align__(256) __half g_u_hi [(size_t)M_ROWS * K_DIM];
__device__ __align__(256) __half g_u_lo [(size_t)M_ROWS * K_DIM];
__device__ __align__(256) __half g_Wdt_h[(size_t)1024  * K_DIM];
__device__ __align__(256) __half g_WB_h [(size_t)DN    * K_DIM];
__device__ __align__(256) __half g_WC_h [(size_t)DN    * K_DIM];
__device__ __align__(256) float  g_dt  [(size_t)M_ROWS * 1024];
__device__ __align__(256) __half g_Bt16[(size_t)M_ROWS * DN];
__device__ __align__(256) __half g_Ct16[(size_t)M_ROWS * DN];

// ---------------------------------------------------------------------------
// Helpers (family-portable PTX only: cp.async, ldmatrix, mma.sync)
// ---------------------------------------------------------------------------
__device__ __forceinline__ uint32_t smem_u32(const void* p) {
    uint32_t a;
    asm("{ .reg .u64 t; cvta.to.shared.u64 t, %1; cvt.u32.u64 %0, t; }"
        : "=r"(a) : "l"(p));
    return a;
}
__device__ __forceinline__ void cp16(uint32_t s, const void* g) {
    asm volatile("cp.async.cg.shared.global [%0], [%1], 16;" :: "r"(s), "l"(g));
}
#define CP_COMMIT() asm volatile("cp.async.commit_group;" ::: "memory")
#define CP_WAIT2()  asm volatile("cp.async.wait_group 2;"  ::: "memory")
#define CP_WAIT0()  asm volatile("cp.async.wait_group 0;"  ::: "memory")

__device__ __forceinline__ void ldsm4(uint32_t* r, uint32_t addr) {
    asm volatile("ldmatrix.sync.aligned.m8n8.x4.shared.b16 {%0,%1,%2,%3}, [%4];"
                 : "=r"(r[0]), "=r"(r[1]), "=r"(r[2]), "=r"(r[3]) : "r"(addr));
}
__device__ __forceinline__ void mma16816(float* d, const uint32_t* a, const uint32_t* b) {
    asm volatile(
        "mma.sync.aligned.m16n8k16.row.col.f32.f16.f16.f32 "
        "{%0,%1,%2,%3}, {%4,%5,%6,%7}, {%8,%9}, {%0,%1,%2,%3};"
        : "+f"(d[0]), "+f"(d[1]), "+f"(d[2]), "+f"(d[3])
        : "r"(a[0]), "r"(a[1]), "r"(a[2]), "r"(a[3]), "r"(b[0]), "r"(b[1]));
}

// ---------------------------------------------------------------------------
// Splits. mode 0: u -> (hi, lo) fp16.  mode 1/2/3: W_dt/W_B/W_C -> hi fp16.
// ---------------------------------------------------------------------------
__global__ __launch_bounds__(256)
void split_kernel(const float* __restrict__ src, int mode, int n4)
{
    int i = blockIdx.x * 256 + threadIdx.x;
    if (i >= n4) return;
    float4 x = ((const float4*)src)[i];
    float xs[4] = {x.x, x.y, x.z, x.w};
    __half h[4];
    #pragma unroll
    for (int j = 0; j < 4; j++) h[j] = __float2half_rn(xs[j]);

    if (mode == 0) {
        __half l[4];
        #pragma unroll
        for (int j = 0; j < 4; j++)
            l[j] = __float2half_rn(xs[j] - __half2float(h[j]));
        *((uint2*)(g_u_hi + 4 * (size_t)i)) = *(uint2*)h;
        *((uint2*)(g_u_lo + 4 * (size_t)i)) = *(uint2*)l;
    } else {
        __half* hi = (mode == 1) ? g_Wdt_h : (mode == 2) ? g_WB_h : g_WC_h;
        *((uint2*)(hi + 4 * (size_t)i)) = *(uint2*)h;
    }
}

// ---------------------------------------------------------------------------
// fp16 mma.sync GEMM, 2-term split: out = (uh + ul) * Wh^T + bias
//   Block 128x256, 8 warps (2x4), warp tile 64x64, K-chunk 32, 4-stage.
//   smem rows padded to 80B -> conflict-free ldmatrix.
// WHICH: 0 -> Wdt -> g_dt (fp32 + softplus); 1 -> WB -> g_Bt16; 2 -> WC -> g_Ct16
// ---------------------------------------------------------------------------
#define ROW_B     80          // bytes per smem row (64 data + 16 pad)
#define A_HI_OFF  0
#define A_LO_OFF  10240       // 128*80
#define B_HI_OFF  20480
#define STAGE_SZ  40960       // + 256*80
#define NSTAGE    4
#define SMEM_GEMM (NSTAGE * STAGE_SZ)   // 160 KB

template <int WHICH>
__global__ __launch_bounds__(256, 1)
void gemm_mma(const float* __restrict__ bias1,
              const float* __restrict__ bias2, int Ncols)
{
    extern __shared__ char smem[];
    const uint32_t sb = smem_u32(smem);
    const int tid = threadIdx.x;
    const int wid = tid >> 5;
    const int lane = tid & 31;
    const int mBase = blockIdx.x * 128;
    const int nBase = blockIdx.y * 256;
    const int warp_m = (wid >> 2) * 64;   // 0 or 64
    const int warp_n = (wid & 3) * 64;    // 0,64,128,192

    const __half* Ah = g_u_hi;
    const __half* Al = g_u_lo;
    const __half* Bh = (WHICH == 0) ? g_Wdt_h : (WHICH == 1) ? g_WB_h : g_WC_h;

    // ---- stage loader: A[128x32] hi/lo + B[256x32] hi  (fp16)
    auto load_stage = [&](int s, int k0) {
        const uint32_t st = sb + (uint32_t)s * STAGE_SZ;
        #pragma unroll
        for (int i = 0; i < 2; i++) {
            int idx = i * 256 + tid;
            int row = idx >> 2, c = idx & 3;
            uint32_t so = (uint32_t)(row * ROW_B + c * 16);
            size_t go = (size_t)(mBase + row) * K_DIM + k0 + c * 8;
            cp16(st + A_HI_OFF + so, Ah + go);
            cp16(st + A_LO_OFF + so, Al + go);
        }
        #pragma unroll
        for (int i = 0; i < 4; i++) {
            int idx = i * 256 + tid;
            int row = idx >> 2, c = idx & 3;
            uint32_t so = (uint32_t)(row * ROW_B + c * 16);
            size_t go = (size_t)(nBase + row) * K_DIM + k0 + c * 8;
            cp16(st + B_HI_OFF + so, Bh + go);
        }
    };

    float acc[4][8][4];
    #pragma unroll
    for (int i = 0; i < 4; i++)
        #pragma unroll
        for (int j = 0; j < 8; j++)
            #pragma unroll
            for (int q = 0; q < 4; q++)
                acc[i][j][q] = 0.0f;

    // ldmatrix per-lane address components
    const int aRow  = lane & 15;
    const int aHalf = lane >> 4;
    const int bJ    = lane & 7;
    const int bG    = lane >> 3;
    const int bRow  = (bG >> 1) * 8 + bJ;
    const int bHalf = bG & 1;

    load_stage(0, 0);  CP_COMMIT();
    load_stage(1, 32); CP_COMMIT();
    load_stage(2, 64); CP_COMMIT();

    const int NCHUNK = K_DIM / 32;        // 32
    for (int c = 0; c < NCHUNK; c++) {
        CP_WAIT2();                       // oldest group (stage c) complete
        __syncthreads();                  // collective visibility

        // prefetch stage c+3 (overwrites stage consumed at iter c-1)
        if (c + 3 < NCHUNK) load_stage((c + 3) & 3, (c + 3) * 32);
        CP_COMMIT();                      // uniform group accounting

        const uint32_t st = sb + (uint32_t)(c & 3) * STAGE_SZ;
        #pragma unroll
        for (int ks = 0; ks < 2; ks++) {
            const uint32_t kOff = ks * 32;
            uint32_t ah[4][4], al[4][4], bh[8][2];
            #pragma unroll
            for (int i = 0; i < 4; i++) {
                uint32_t ao = (uint32_t)((warp_m + i * 16 + aRow) * ROW_B)
                              + kOff + aHalf * 16;
                ldsm4(ah[i], st + A_HI_OFF + ao);
                ldsm4(al[i], st + A_LO_OFF + ao);
            }
            #pragma unroll
            for (int j = 0; j < 4; j++) {
                uint32_t bo = (uint32_t)((warp_n + j * 16 + bRow) * ROW_B)
                              + kOff + bHalf * 16;
                uint32_t rh[4];
                ldsm4(rh, st + B_HI_OFF + bo);
                bh[2*j][0] = rh[0]; bh[2*j][1] = rh[1];
                bh[2*j+1][0] = rh[2]; bh[2*j+1][1] = rh[3];
            }
            #pragma unroll
            for (int i = 0; i < 4; i++)
                #pragma unroll
                for (int j = 0; j < 8; j++) {
                    mma16816(acc[i][j], ah[i], bh[j]);
                    mma16816(acc[i][j], al[i], bh[j]);
                }
        }
        __syncthreads();                  // all reads of stage done before next refill
    }
    CP_WAIT0();

    // ---- epilogue
    const int r0 = (lane >> 2);
    const int c0 = (lane & 3) * 2;
    #pragma unroll
    for (int i = 0; i < 4; i++) {
        const int gr0 = mBase + warp_m + i * 16 + r0;
        #pragma unroll
        for (int j = 0; j < 8; j++) {
            const int gc = nBase + warp_n + j * 8 + c0;
            float v0 = acc[i][j][0] + bias1[gc];
            float v1 = acc[i][j][1] + bias1[gc + 1];
            float v2 = acc[i][j][2] + bias1[gc];
            float v3 = acc[i][j][3] + bias1[gc + 1];
            if (WHICH == 0) {
                v0 += bias2[gc];     v1 += bias2[gc + 1];
                v2 += bias2[gc];     v3 += bias2[gc + 1];
                v0 = fmaxf(v0, 0.0f) + log1pf(__expf(-fabsf(v0)));
                v1 = fmaxf(v1, 0.0f) + log1pf(__expf(-fabsf(v1)));
                v2 = fmaxf(v2, 0.0f) + log1pf(__expf(-fabsf(v2)));
                v3 = fmaxf(v3, 0.0f) + log1pf(__expf(-fabsf(v3)));
                *(float2*)(g_dt + (size_t)gr0       * Ncols + gc) = make_float2(v0, v1);
                *(float2*)(g_dt + (size_t)(gr0 + 8) * Ncols + gc) = make_float2(v2, v3);
            } else {
                __half* out = (WHICH == 1) ? g_Bt16 : g_Ct16;
                *(__half2*)(out + (size_t)gr0       * Ncols + gc) = __floats2half2_rn(v0, v1);
                *(__half2*)(out + (size_t)(gr0 + 8) * Ncols + gc) = __floats2half2_rn(v2, v3);
            }
        }
    }
}

// ---------------------------------------------------------------------------
// Scan: one thread per (b, d, n). Block = 8 d x 16 n = 128 thr. Grid = 256.
// ---------------------------------------------------------------------------
__global__ __launch_bounds__(128)
void scan_kernel(const float* __restrict__ u,
                 const float* __restrict__ logA,
                 const float* __restrict__ Dskip,
                 float* __restrict__ y)
{
    const int tid  = threadIdx.x;         // 0..127
    const int n    = tid & 15;
    const int dl   = tid >> 4;            // 0..7
    const int blk  = blockIdx.x;          // 0..255
    const int b    = blk >> 7;
    const int dblk = blk & 127;
    const int d    = dblk * 8 + dl;

    const float Aval = -__expf(logA[d * 16 + n]);
    const float invA = 1.0f / Aval;
    const float dsk  = Dskip[d];

    const float*  uB  = u      + (size_t)b * 2048 * 1024;
    const float*  dtB = g_dt   + (size_t)b * 2048 * 1024;
    const __half* BtB = g_Bt16 + (size_t)b * 2048 * DN;
    const __half* CtB = g_Ct16 + (size_t)b * 2048 * DN;
    float*        yB  = y      + (size_t)b * 2048 * 1024;

    const int off = dblk * 128 + tid;     // (d*16+n) within a DN row

    float h = 0.0f;
    #pragma unroll 2
    for (int t = 0; t < 2048; ++t) {
        const float uv  = uB [t * 1024 + d];
        const float dtv = dtB[t * 1024 + d];
        const float Btv = __half2float(BtB[(size_t)t * DN + off]);
        const float Ctv = __half2float(CtB[(size_t)t * DN + off]);

        const float a = __expf(dtv * Aval);
        const float x = (a - 1.0f) * invA * Btv * uv;
        h = fmaf(a, h, x);

        float p = Ctv * h;
        p += __shfl_down_sync(0xffffffffu, p, 8, 16);
        p += __shfl_down_sync(0xffffffffu, p, 4, 16);
        p += __shfl_down_sync(0xffffffffu, p, 2, 16);
        p += __shfl_down_sync(0xffffffffu, p, 1, 16);

        if (n == 0)
            yB[t * 1024 + d] = p + dsk * uv;
    }
}

// ---------------------------------------------------------------------------
extern "C" void kernel_launch(void* const* d_in, const int* in_sizes, int n_in,
                              void* d_out, int out_size)
{
    const float* u       = (const float*)d_in[0];
    const float* log_A   = (const float*)d_in[1];
    const float* D_skip  = (const float*)d_in[2];
    const float* dt_bias = (const float*)d_in[3];
    const float* W_dt    = (const float*)d_in[4];
    const float* b_dt    = (const float*)d_in[5];
    const float* W_B     = (const float*)d_in[6];
    const float* b_B     = (const float*)d_in[7];
    const float* W_C     = (const float*)d_in[8];
    const float* b_C     = (const float*)d_in[9];
    float* y = (float*)d_out;

    cudaFuncSetAttribute(gemm_mma<0>, cudaFuncAttributeMaxDynamicSharedMemorySize, SMEM_GEMM);
    cudaFuncSetAttribute(gemm_mma<1>, cudaFuncAttributeMaxDynamicSharedMemorySize, SMEM_GEMM);
    cudaFuncSetAttribute(gemm_mma<2>, cudaFuncAttributeMaxDynamicSharedMemorySize, SMEM_GEMM);

    // fp32 -> fp16 splits (u: hi+lo, weights: hi only)
    split_kernel<<<(M_ROWS * K_DIM / 4) / 256, 256>>>(u,    0, M_ROWS * K_DIM / 4);
    split_kernel<<<(1024 * K_DIM   / 4) / 256, 256>>>(W_dt, 1, 1024 * K_DIM / 4);
    split_kernel<<<(DN * K_DIM     / 4) / 256, 256>>>(W_B,  2, DN * K_DIM / 4);
    split_kernel<<<(DN * K_DIM     / 4) / 256, 256>>>(W_C,  3, DN * K_DIM / 4);

    // tensor-core GEMMs (grid.x = M fastest for weight L2 reuse)
    gemm_mma<0><<<dim3(32, 4),  256, SMEM_GEMM>>>(b_dt, dt_bias, 1024);
    gemm_mma<1><<<dim3(32, 64), 256, SMEM_GEMM>>>(b_B,  nullptr, DN);
    gemm_mma<2><<<dim3(32, 64), 256, SMEM_GEMM>>>(b_C,  nullptr, DN);

    // fused discretization + recurrent scan + skip
    scan_kernel<<<256, 128>>>(u, log_A, D_skip, y);
}

// round 6
// speedup vs baseline: 4.9215x; 1.2478x over previous
#include <cuda_runtime.h>
#include <cuda_fp16.h>
#include <math.h>
#include <stdint.h>

// Problem constants: B=2, L=2048, D=1024, N=16
#define M_ROWS 4096
#define K_DIM  1024
#define DN     16384

// ---------------------------------------------------------------------------
// Device scratch
// ---------------------------------------------------------------------------
__device__ __align__(256) __half g_u_hi [(size_t)M_ROWS * K_DIM];
__device__ __align__(256) __half g_u_lo [(size_t)M_ROWS * K_DIM];
__device__ __align__(256) __half g_Wdt_h[(size_t)1024  * K_DIM];
__device__ __align__(256) __half g_WB_h [(size_t)DN    * K_DIM];
__device__ __align__(256) __half g_WC_h [(size_t)DN    * K_DIM];
__device__ __align__(256) float  g_dt  [(size_t)M_ROWS * 1024];
__device__ __align__(256) __half g_Bt16[(size_t)M_ROWS * DN];
__device__ __align__(256) __half g_Ct16[(size_t)M_ROWS * DN];

// ---------------------------------------------------------------------------
// Helpers (family-portable PTX only)
// ---------------------------------------------------------------------------
__device__ __forceinline__ uint32_t smem_u32(const void* p) {
    uint32_t a;
    asm("{ .reg .u64 t; cvta.to.shared.u64 t, %1; cvt.u32.u64 %0, t; }"
        : "=r"(a) : "l"(p));
    return a;
}
__device__ __forceinline__ void cp16(uint32_t s, const void* g) {
    asm volatile("cp.async.cg.shared.global [%0], [%1], 16;" :: "r"(s), "l"(g));
}
#define CP_COMMIT() asm volatile("cp.async.commit_group;" ::: "memory")
#define CP_WAIT3()  asm volatile("cp.async.wait_group 3;"  ::: "memory")
#define CP_WAIT0()  asm volatile("cp.async.wait_group 0;"  ::: "memory")

__device__ __forceinline__ void ldsm4(uint32_t* r, uint32_t addr) {
    asm volatile("ldmatrix.sync.aligned.m8n8.x4.shared.b16 {%0,%1,%2,%3}, [%4];"
                 : "=r"(r[0]), "=r"(r[1]), "=r"(r[2]), "=r"(r[3]) : "r"(addr));
}
__device__ __forceinline__ void mma16816(float* d, const uint32_t* a, const uint32_t* b) {
    asm volatile(
        "mma.sync.aligned.m16n8k16.row.col.f32.f16.f16.f32 "
        "{%0,%1,%2,%3}, {%4,%5,%6,%7}, {%8,%9}, {%0,%1,%2,%3};"
        : "+f"(d[0]), "+f"(d[1]), "+f"(d[2]), "+f"(d[3])
        : "r"(a[0]), "r"(a[1]), "r"(a[2]), "r"(a[3]), "r"(b[0]), "r"(b[1]));
}

// ---------------------------------------------------------------------------
// Splits. mode 0: u -> (hi, lo) fp16.  mode 1/2/3: W_dt/W_B/W_C -> fp16.
// ---------------------------------------------------------------------------
__global__ __launch_bounds__(256)
void split_kernel(const float* __restrict__ src, int mode, int n4)
{
    int i = blockIdx.x * 256 + threadIdx.x;
    if (i >= n4) return;
    float4 x = ((const float4*)src)[i];
    float xs[4] = {x.x, x.y, x.z, x.w};
    __half h[4];
    #pragma unroll
    for (int j = 0; j < 4; j++) h[j] = __float2half_rn(xs[j]);

    if (mode == 0) {
        __half l[4];
        #pragma unroll
        for (int j = 0; j < 4; j++)
            l[j] = __float2half_rn(xs[j] - __half2float(h[j]));
        *((uint2*)(g_u_hi + 4 * (size_t)i)) = *(uint2*)h;
        *((uint2*)(g_u_lo + 4 * (size_t)i)) = *(uint2*)l;
    } else {
        __half* hi = (mode == 1) ? g_Wdt_h : (mode == 2) ? g_WB_h : g_WC_h;
        *((uint2*)(hi + 4 * (size_t)i)) = *(uint2*)h;
    }
}

// ---------------------------------------------------------------------------
// fp16 mma.sync GEMM.
//   TERMS=1: out = uh * W^T       (B/C path, fp16 output)
//   TERMS=2: out = (uh+ul) * W^T  (dt path, fp32 + softplus)
// Block 128x256, 8 warps, warp tile 64x64, K-chunk 32, 5-stage cp.async,
// ONE barrier per chunk. Padded smem rows (80B) -> conflict-free ldmatrix.
// DTPATH=false merges WB and WC: grid.y in [0,128), y>=64 -> C.
// ---------------------------------------------------------------------------
#define ROW_B     80
#define NSTAGE    5

template <int TERMS>
__global__ __launch_bounds__(256, 1)
void gemm_mma(const float* __restrict__ biasB,
              const float* __restrict__ biasC,
              const float* __restrict__ bias2)
{
    constexpr int A_BYTES  = 128 * ROW_B;                  // 10240
    constexpr int B_OFF    = TERMS * A_BYTES;              // after A hi (+lo)
    constexpr int STAGE_SZ = B_OFF + 256 * ROW_B;          // 30720 / 40960

    extern __shared__ char smem[];
    const uint32_t sb = smem_u32(smem);
    const int tid = threadIdx.x;
    const int wid = tid >> 5;
    const int lane = tid & 31;
    const int mBase = blockIdx.x * 128;
    const int warp_m = (wid >> 2) * 64;
    const int warp_n = (wid & 3) * 64;

    const __half* Ah = g_u_hi;
    const __half* Al = g_u_lo;

    const __half* W;
    const float*  bias1;
    __half* out16 = nullptr;
    int nBase;                            // column base in the output
    int Ncols;
    if (TERMS == 2) {                     // dt path
        W = g_Wdt_h; bias1 = biasB; nBase = blockIdx.y * 256; Ncols = 1024;
    } else {
        const int byg = blockIdx.y;       // 0..127
        const bool isC = byg >= 64;
        W     = isC ? g_WC_h  : g_WB_h;
        out16 = isC ? g_Ct16  : g_Bt16;
        bias1 = isC ? biasC   : biasB;
        nBase = (byg & 63) * 256;
        Ncols = DN;
    }

    auto load_stage = [&](int s, int k0) {
        const uint32_t st = sb + (uint32_t)s * STAGE_SZ;
        #pragma unroll
        for (int i = 0; i < 2; i++) {
            int idx = i * 256 + tid;
            int row = idx >> 2, c = idx & 3;
            uint32_t so = (uint32_t)(row * ROW_B + c * 16);
            size_t go = (size_t)(mBase + row) * K_DIM + k0 + c * 8;
            cp16(st + so, Ah + go);
            if (TERMS == 2) cp16(st + A_BYTES + so, Al + go);
        }
        #pragma unroll
        for (int i = 0; i < 4; i++) {
            int idx = i * 256 + tid;
            int row = idx >> 2, c = idx & 3;
            uint32_t so = (uint32_t)(row * ROW_B + c * 16);
            size_t go = (size_t)(nBase + row) * K_DIM + k0 + c * 8;
            cp16(st + B_OFF + so, W + go);
        }
    };

    float acc[4][8][4];
    #pragma unroll
    for (int i = 0; i < 4; i++)
        #pragma unroll
        for (int j = 0; j < 8; j++)
            #pragma unroll
            for (int q = 0; q < 4; q++)
                acc[i][j][q] = 0.0f;

    const int aRow  = lane & 15;
    const int aHalf = lane >> 4;
    const int bJ    = lane & 7;
    const int bG    = lane >> 3;
    const int bRow  = (bG >> 1) * 8 + bJ;
    const int bHalf = bG & 1;

    load_stage(0, 0);   CP_COMMIT();
    load_stage(1, 32);  CP_COMMIT();
    load_stage(2, 64);  CP_COMMIT();
    load_stage(3, 96);  CP_COMMIT();

    const int NCHUNK = K_DIM / 32;        // 32
    for (int c = 0; c < NCHUNK; c++) {
        CP_WAIT3();                       // oldest outstanding group (chunk c) done
        __syncthreads();                  // visibility + protects stage overwrite

        if (c + 4 < NCHUNK) load_stage((c + 4) % NSTAGE, (c + 4) * 32);
        CP_COMMIT();

        const uint32_t st = sb + (uint32_t)(c % NSTAGE) * STAGE_SZ;
        #pragma unroll
        for (int ks = 0; ks < 2; ks++) {
            const uint32_t kOff = ks * 32;
            uint32_t ah[4][4], al[4][4], bh[8][2];
            #pragma unroll
            for (int i = 0; i < 4; i++) {
                uint32_t ao = (uint32_t)((warp_m + i * 16 + aRow) * ROW_B)
                              + kOff + aHalf * 16;
                ldsm4(ah[i], st + ao);
                if (TERMS == 2) ldsm4(al[i], st + A_BYTES + ao);
            }
            #pragma unroll
            for (int j = 0; j < 4; j++) {
                uint32_t bo = (uint32_t)((warp_n + j * 16 + bRow) * ROW_B)
                              + kOff + bHalf * 16;
                uint32_t rh[4];
                ldsm4(rh, st + B_OFF + bo);
                bh[2*j][0] = rh[0]; bh[2*j][1] = rh[1];
                bh[2*j+1][0] = rh[2]; bh[2*j+1][1] = rh[3];
            }
            #pragma unroll
            for (int i = 0; i < 4; i++)
                #pragma unroll
                for (int j = 0; j < 8; j++) {
                    mma16816(acc[i][j], ah[i], bh[j]);
                    if (TERMS == 2) mma16816(acc[i][j], al[i], bh[j]);
                }
        }
        // no second barrier: next iteration's top barrier orders the overwrite
    }
    CP_WAIT0();

    // ---- epilogue
    const int r0 = (lane >> 2);
    const int c0 = (lane & 3) * 2;
    #pragma unroll
    for (int i = 0; i < 4; i++) {
        const int gr0 = mBase + warp_m + i * 16 + r0;
        #pragma unroll
        for (int j = 0; j < 8; j++) {
            const int gc = nBase + warp_n + j * 8 + c0;
            float v0 = acc[i][j][0] + bias1[gc];
            float v1 = acc[i][j][1] + bias1[gc + 1];
            float v2 = acc[i][j][2] + bias1[gc];
            float v3 = acc[i][j][3] + bias1[gc + 1];
            if (TERMS == 2) {
                v0 += bias2[gc];     v1 += bias2[gc + 1];
                v2 += bias2[gc];     v3 += bias2[gc + 1];
                v0 = fmaxf(v0, 0.0f) + log1pf(__expf(-fabsf(v0)));
                v1 = fmaxf(v1, 0.0f) + log1pf(__expf(-fabsf(v1)));
                v2 = fmaxf(v2, 0.0f) + log1pf(__expf(-fabsf(v2)));
                v3 = fmaxf(v3, 0.0f) + log1pf(__expf(-fabsf(v3)));
                *(float2*)(g_dt + (size_t)gr0       * 1024 + gc) = make_float2(v0, v1);
                *(float2*)(g_dt + (size_t)(gr0 + 8) * 1024 + gc) = make_float2(v2, v3);
            } else {
                *(__half2*)(out16 + (size_t)gr0       * DN + gc) = __floats2half2_rn(v0, v1);
                *(__half2*)(out16 + (size_t)(gr0 + 8) * DN + gc) = __floats2half2_rn(v2, v3);
            }
        }
    }
}

// ---------------------------------------------------------------------------
// Scan: one thread per (b, d, n). Block = 8 d x 16 n = 128 thr. Grid = 256.
// ---------------------------------------------------------------------------
__global__ __launch_bounds__(128)
void scan_kernel(const float* __restrict__ u,
                 const float* __restrict__ logA,
                 const float* __restrict__ Dskip,
                 float* __restrict__ y)
{
    const int tid  = threadIdx.x;
    const int n    = tid & 15;
    const int dl   = tid >> 4;
    const int blk  = blockIdx.x;
    const int b    = blk >> 7;
    const int dblk = blk & 127;
    const int d    = dblk * 8 + dl;

    const float Aval = -__expf(logA[d * 16 + n]);
    const float invA = 1.0f / Aval;
    const float dsk  = Dskip[d];

    const float*  uB  = u      + (size_t)b * 2048 * 1024;
    const float*  dtB = g_dt   + (size_t)b * 2048 * 1024;
    const __half* BtB = g_Bt16 + (size_t)b * 2048 * DN;
    const __half* CtB = g_Ct16 + (size_t)b * 2048 * DN;
    float*        yB  = y      + (size_t)b * 2048 * 1024;

    const int off = dblk * 128 + tid;

    float h = 0.0f;
    #pragma unroll 2
    for (int t = 0; t < 2048; ++t) {
        const float uv  = uB [t * 1024 + d];
        const float dtv = dtB[t * 1024 + d];
        const float Btv = __half2float(BtB[(size_t)t * DN + off]);
        const float Ctv = __half2float(CtB[(size_t)t * DN + off]);

        const float a = __expf(dtv * Aval);
        const float x = (a - 1.0f) * invA * Btv * uv;
        h = fmaf(a, h, x);

        float p = Ctv * h;
        p += __shfl_down_sync(0xffffffffu, p, 8, 16);
        p += __shfl_down_sync(0xffffffffu, p, 4, 16);
        p += __shfl_down_sync(0xffffffffu, p, 2, 16);
        p += __shfl_down_sync(0xffffffffu, p, 1, 16);

        if (n == 0)
            yB[t * 1024 + d] = p + dsk * uv;
    }
}

// ---------------------------------------------------------------------------
extern "C" void kernel_launch(void* const* d_in, const int* in_sizes, int n_in,
                              void* d_out, int out_size)
{
    const float* u       = (const float*)d_in[0];
    const float* log_A   = (const float*)d_in[1];
    const float* D_skip  = (const float*)d_in[2];
    const float* dt_bias = (const float*)d_in[3];
    const float* W_dt    = (const float*)d_in[4];
    const float* b_dt    = (const float*)d_in[5];
    const float* W_B     = (const float*)d_in[6];
    const float* b_B     = (const float*)d_in[7];
    const float* W_C     = (const float*)d_in[8];
    const float* b_C     = (const float*)d_in[9];
    float* y = (float*)d_out;

    const int SMEM1 = NSTAGE * (128 * ROW_B + 256 * ROW_B);        // 153600
    const int SMEM2 = NSTAGE * (2 * 128 * ROW_B + 256 * ROW_B);    // 204800
    cudaFuncSetAttribute(gemm_mma<1>, cudaFuncAttributeMaxDynamicSharedMemorySize, SMEM1);
    cudaFuncSetAttribute(gemm_mma<2>, cudaFuncAttributeMaxDynamicSharedMemorySize, SMEM2);

    // fp32 -> fp16 splits
    split_kernel<<<(M_ROWS * K_DIM / 4) / 256, 256>>>(u,    0, M_ROWS * K_DIM / 4);
    split_kernel<<<(1024 * K_DIM   / 4) / 256, 256>>>(W_dt, 1, 1024 * K_DIM / 4);
    split_kernel<<<(DN * K_DIM     / 4) / 256, 256>>>(W_B,  2, DN * K_DIM / 4);
    split_kernel<<<(DN * K_DIM     / 4) / 256, 256>>>(W_C,  3, DN * K_DIM / 4);

    // dt GEMM (2-term, fp32+softplus out)
    gemm_mma<2><<<dim3(32, 4),   256, SMEM2>>>(b_dt, nullptr, dt_bias);
    // merged B+C GEMM (1-term, fp16 out)
    gemm_mma<1><<<dim3(32, 128), 256, SMEM1>>>(b_B,  b_C,     nullptr);

    // fused discretization + recurrent scan + skip
    scan_kernel<<<256, 128>>>(u, log_A, D_skip, y);
}

// round 7
// speedup vs baseline: 4.9556x; 1.0069x over previous
#include <cuda_runtime.h>
#include <cuda_fp16.h>
#include <math.h>
#include <stdint.h>

// Problem constants: B=2, L=2048, D=1024, N=16
#define M_ROWS 4096
#define K_DIM  1024
#define DN     16384

// ---------------------------------------------------------------------------
// Device scratch
// ---------------------------------------------------------------------------
__device__ __align__(256) __half g_u_hi [(size_t)M_ROWS * K_DIM];
__device__ __align__(256) __half g_u_lo [(size_t)M_ROWS * K_DIM];
__device__ __align__(256) __half g_Wdt_h[(size_t)1024  * K_DIM];
__device__ __align__(256) __half g_WB_h [(size_t)DN    * K_DIM];
__device__ __align__(256) __half g_WC_h [(size_t)DN    * K_DIM];
__device__ __align__(256) float  g_dt  [(size_t)M_ROWS * 1024];
__device__ __align__(256) __half g_Bt16[(size_t)M_ROWS * DN];
__device__ __align__(256) __half g_Ct16[(size_t)M_ROWS * DN];

// ---------------------------------------------------------------------------
// Helpers (family-portable PTX only)
// ---------------------------------------------------------------------------
__device__ __forceinline__ uint32_t smem_u32(const void* p) {
    uint32_t a;
    asm("{ .reg .u64 t; cvta.to.shared.u64 t, %1; cvt.u32.u64 %0, t; }"
        : "=r"(a) : "l"(p));
    return a;
}
__device__ __forceinline__ void cp16(uint32_t s, const void* g) {
    asm volatile("cp.async.cg.shared.global [%0], [%1], 16;" :: "r"(s), "l"(g));
}
#define CP_COMMIT() asm volatile("cp.async.commit_group;" ::: "memory")
#define CP_WAIT3()  asm volatile("cp.async.wait_group 3;"  ::: "memory")
#define CP_WAIT0()  asm volatile("cp.async.wait_group 0;"  ::: "memory")

__device__ __forceinline__ void ldsm4(uint32_t* r, uint32_t addr) {
    asm volatile("ldmatrix.sync.aligned.m8n8.x4.shared.b16 {%0,%1,%2,%3}, [%4];"
                 : "=r"(r[0]), "=r"(r[1]), "=r"(r[2]), "=r"(r[3]) : "r"(addr));
}
__device__ __forceinline__ void mma16816(float* d, const uint32_t* a, const uint32_t* b) {
    asm volatile(
        "mma.sync.aligned.m16n8k16.row.col.f32.f16.f16.f32 "
        "{%0,%1,%2,%3}, {%4,%5,%6,%7}, {%8,%9}, {%0,%1,%2,%3};"
        : "+f"(d[0]), "+f"(d[1]), "+f"(d[2]), "+f"(d[3])
        : "r"(a[0]), "r"(a[1]), "r"(a[2]), "r"(a[3]), "r"(b[0]), "r"(b[1]));
}

// ---------------------------------------------------------------------------
// Merged split kernel: one launch converts all fp32 sources to fp16.
// Regions (in float4 units): u (hi+lo) | W_dt | W_B | W_C
// ---------------------------------------------------------------------------
#define U4    ((M_ROWS * K_DIM) / 4)          // 1048576
#define WDT4  ((1024 * K_DIM) / 4)            //  262144
#define WBC4  (((size_t)DN * K_DIM) / 4)      // 4194304
#define T0    (U4)
#define T1    (T0 + WDT4)
#define T2    (T1 + (int)WBC4)
#define T3    (T2 + (int)WBC4)                // 9699328

__global__ __launch_bounds__(256)
void split_all_kernel(const float* __restrict__ u,
                      const float* __restrict__ W_dt,
                      const float* __restrict__ W_B,
                      const float* __restrict__ W_C)
{
    int i = blockIdx.x * 256 + threadIdx.x;
    if (i >= T3) return;

    const float* src;
    __half* dst;
    int idx;
    bool split2 = false;
    if (i < T0)      { src = u;    dst = g_u_hi;  idx = i;       split2 = true; }
    else if (i < T1) { src = W_dt; dst = g_Wdt_h; idx = i - T0; }
    else if (i < T2) { src = W_B;  dst = g_WB_h;  idx = i - T1; }
    else             { src = W_C;  dst = g_WC_h;  idx = i - T2; }

    float4 x = ((const float4*)src)[idx];
    float xs[4] = {x.x, x.y, x.z, x.w};
    __half h[4];
    #pragma unroll
    for (int j = 0; j < 4; j++) h[j] = __float2half_rn(xs[j]);
    *((uint2*)(dst + 4 * (size_t)idx)) = *(uint2*)h;

    if (split2) {
        __half l[4];
        #pragma unroll
        for (int j = 0; j < 4; j++)
            l[j] = __float2half_rn(xs[j] - __half2float(h[j]));
        *((uint2*)(g_u_lo + 4 * (size_t)idx)) = *(uint2*)l;
    }
}

// ---------------------------------------------------------------------------
// fp16 mma.sync GEMM. 512 threads, 16 warps (2 m x 8 n), warp tile 64x32.
//   TERMS=1: out = uh * W^T       (B/C path, fp16 output, merged B+C grid)
//   TERMS=2: out = (uh+ul) * W^T  (dt path, fp32 + softplus)
// Block 128x256, K-chunk 32, 5-stage cp.async, ONE barrier per chunk.
// ---------------------------------------------------------------------------
#define ROW_B     80
#define NSTAGE    5

template <int TERMS>
__global__ __launch_bounds__(512, 1)
void gemm_mma(const float* __restrict__ biasB,
              const float* __restrict__ biasC,
              const float* __restrict__ bias2)
{
    constexpr int A_BYTES  = 128 * ROW_B;                  // 10240
    constexpr int B_OFF    = TERMS * A_BYTES;
    constexpr int STAGE_SZ = B_OFF + 256 * ROW_B;          // 30720 / 40960

    extern __shared__ char smem[];
    const uint32_t sb = smem_u32(smem);
    const int tid = threadIdx.x;
    const int wid = tid >> 5;             // 0..15
    const int lane = tid & 31;
    const int mBase = blockIdx.x * 128;
    const int warp_m = (wid >> 3) * 64;   // 0 or 64
    const int warp_n = (wid & 7) * 32;    // 0..224

    const __half* Ah = g_u_hi;
    const __half* Al = g_u_lo;

    const __half* W;
    const float*  bias1;
    __half* out16 = nullptr;
    int nBase;
    if (TERMS == 2) {
        W = g_Wdt_h; bias1 = biasB; nBase = blockIdx.y * 256;
    } else {
        const int byg = blockIdx.y;       // 0..127
        const bool isC = byg >= 64;
        W     = isC ? g_WC_h  : g_WB_h;
        out16 = isC ? g_Ct16  : g_Bt16;
        bias1 = isC ? biasC   : biasB;
        nBase = (byg & 63) * 256;
    }

    auto load_stage = [&](int s, int k0) {
        const uint32_t st = sb + (uint32_t)s * STAGE_SZ;
        {   // A: 128 rows x 64B -> 512 cp16, 1 per thread
            int row = tid >> 2, c = tid & 3;
            uint32_t so = (uint32_t)(row * ROW_B + c * 16);
            size_t go = (size_t)(mBase + row) * K_DIM + k0 + c * 8;
            cp16(st + so, Ah + go);
            if (TERMS == 2) cp16(st + A_BYTES + so, Al + go);
        }
        #pragma unroll
        for (int i = 0; i < 2; i++) {     // B: 256 rows x 64B -> 1024 cp16
            int idx = i * 512 + tid;
            int row = idx >> 2, c = idx & 3;
            uint32_t so = (uint32_t)(row * ROW_B + c * 16);
            size_t go = (size_t)(nBase + row) * K_DIM + k0 + c * 8;
            cp16(st + B_OFF + so, W + go);
        }
    };

    float acc[4][4][4];
    #pragma unroll
    for (int i = 0; i < 4; i++)
        #pragma unroll
        for (int j = 0; j < 4; j++)
            #pragma unroll
            for (int q = 0; q < 4; q++)
                acc[i][j][q] = 0.0f;

    const int aRow  = lane & 15;
    const int aHalf = lane >> 4;
    const int bJ    = lane & 7;
    const int bG    = lane >> 3;
    const int bRow  = (bG >> 1) * 8 + bJ;
    const int bHalf = bG & 1;

    load_stage(0, 0);   CP_COMMIT();
    load_stage(1, 32);  CP_COMMIT();
    load_stage(2, 64);  CP_COMMIT();
    load_stage(3, 96);  CP_COMMIT();

    const int NCHUNK = K_DIM / 32;        // 32
    for (int c = 0; c < NCHUNK; c++) {
        CP_WAIT3();
        __syncthreads();

        if (c + 4 < NCHUNK) load_stage((c + 4) % NSTAGE, (c + 4) * 32);
        CP_COMMIT();

        const uint32_t st = sb + (uint32_t)(c % NSTAGE) * STAGE_SZ;
        #pragma unroll
        for (int ks = 0; ks < 2; ks++) {
            const uint32_t kOff = ks * 32;
            uint32_t ah[4][4], al[4][4], bh[4][2];
            #pragma unroll
            for (int i = 0; i < 4; i++) {
                uint32_t ao = (uint32_t)((warp_m + i * 16 + aRow) * ROW_B)
                              + kOff + aHalf * 16;
                ldsm4(ah[i], st + ao);
                if (TERMS == 2) ldsm4(al[i], st + A_BYTES + ao);
            }
            #pragma unroll
            for (int j = 0; j < 2; j++) { // 2 x ldsm4 -> 4 n-tiles of 8
                uint32_t bo = (uint32_t)((warp_n + j * 16 + bRow) * ROW_B)
                              + kOff + bHalf * 16;
                uint32_t rh[4];
                ldsm4(rh, st + B_OFF + bo);
                bh[2*j][0] = rh[0]; bh[2*j][1] = rh[1];
                bh[2*j+1][0] = rh[2]; bh[2*j+1][1] = rh[3];
            }
            #pragma unroll
            for (int i = 0; i < 4; i++)
                #pragma unroll
                for (int j = 0; j < 4; j++) {
                    mma16816(acc[i][j], ah[i], bh[j]);
                    if (TERMS == 2) mma16816(acc[i][j], al[i], bh[j]);
                }
        }
    }
    CP_WAIT0();

    // ---- epilogue: each warp writes its 64x32 tile
    const int r0 = (lane >> 2);
    const int c0 = (lane & 3) * 2;
    #pragma unroll
    for (int i = 0; i < 4; i++) {
        const int gr0 = mBase + warp_m + i * 16 + r0;
        #pragma unroll
        for (int j = 0; j < 4; j++) {
            const int gc = nBase + warp_n + j * 8 + c0;
            float v0 = acc[i][j][0] + bias1[gc];
            float v1 = acc[i][j][1] + bias1[gc + 1];
            float v2 = acc[i][j][2] + bias1[gc];
            float v3 = acc[i][j][3] + bias1[gc + 1];
            if (TERMS == 2) {
                v0 += bias2[gc];     v1 += bias2[gc + 1];
                v2 += bias2[gc];     v3 += bias2[gc + 1];
                v0 = fmaxf(v0, 0.0f) + log1pf(__expf(-fabsf(v0)));
                v1 = fmaxf(v1, 0.0f) + log1pf(__expf(-fabsf(v1)));
                v2 = fmaxf(v2, 0.0f) + log1pf(__expf(-fabsf(v2)));
                v3 = fmaxf(v3, 0.0f) + log1pf(__expf(-fabsf(v3)));
                *(float2*)(g_dt + (size_t)gr0       * 1024 + gc) = make_float2(v0, v1);
                *(float2*)(g_dt + (size_t)(gr0 + 8) * 1024 + gc) = make_float2(v2, v3);
            } else {
                *(__half2*)(out16 + (size_t)gr0       * DN + gc) = __floats2half2_rn(v0, v1);
                *(__half2*)(out16 + (size_t)(gr0 + 8) * DN + gc) = __floats2half2_rn(v2, v3);
            }
        }
    }
}

// ---------------------------------------------------------------------------
// Scan: one thread per (b, d, n). Block = 8 d x 16 n = 128 thr. Grid = 256.
// ---------------------------------------------------------------------------
__global__ __launch_bounds__(128)
void scan_kernel(const float* __restrict__ u,
                 const float* __restrict__ logA,
                 const float* __restrict__ Dskip,
                 float* __restrict__ y)
{
    const int tid  = threadIdx.x;
    const int n    = tid & 15;
    const int dl   = tid >> 4;
    const int blk  = blockIdx.x;
    const int b    = blk >> 7;
    const int dblk = blk & 127;
    const int d    = dblk * 8 + dl;

    const float Aval = -__expf(logA[d * 16 + n]);
    const float invA = 1.0f / Aval;
    const float dsk  = Dskip[d];

    const float*  uB  = u      + (size_t)b * 2048 * 1024;
    const float*  dtB = g_dt   + (size_t)b * 2048 * 1024;
    const __half* BtB = g_Bt16 + (size_t)b * 2048 * DN;
    const __half* CtB = g_Ct16 + (size_t)b * 2048 * DN;
    float*        yB  = y      + (size_t)b * 2048 * 1024;

    const int off = dblk * 128 + tid;

    float h = 0.0f;
    #pragma unroll 2
    for (int t = 0; t < 2048; ++t) {
        const float uv  = uB [t * 1024 + d];
        const float dtv = dtB[t * 1024 + d];
        const float Btv = __half2float(BtB[(size_t)t * DN + off]);
        const float Ctv = __half2float(CtB[(size_t)t * DN + off]);

        const float a = __expf(dtv * Aval);
        const float x = (a - 1.0f) * invA * Btv * uv;
        h = fmaf(a, h, x);

        float p = Ctv * h;
        p += __shfl_down_sync(0xffffffffu, p, 8, 16);
        p += __shfl_down_sync(0xffffffffu, p, 4, 16);
        p += __shfl_down_sync(0xffffffffu, p, 2, 16);
        p += __shfl_down_sync(0xffffffffu, p, 1, 16);

        if (n == 0)
            yB[t * 1024 + d] = p + dsk * uv;
    }
}

// ---------------------------------------------------------------------------
extern "C" void kernel_launch(void* const* d_in, const int* in_sizes, int n_in,
                              void* d_out, int out_size)
{
    const float* u       = (const float*)d_in[0];
    const float* log_A   = (const float*)d_in[1];
    const float* D_skip  = (const float*)d_in[2];
    const float* dt_bias = (const float*)d_in[3];
    const float* W_dt    = (const float*)d_in[4];
    const float* b_dt    = (const float*)d_in[5];
    const float* W_B     = (const float*)d_in[6];
    const float* b_B     = (const float*)d_in[7];
    const float* W_C     = (const float*)d_in[8];
    const float* b_C     = (const float*)d_in[9];
    float* y = (float*)d_out;

    const int SMEM1 = NSTAGE * (128 * ROW_B + 256 * ROW_B);        // 153600
    const int SMEM2 = NSTAGE * (2 * 128 * ROW_B + 256 * ROW_B);    // 204800
    cudaFuncSetAttribute(gemm_mma<1>, cudaFuncAttributeMaxDynamicSharedMemorySize, SMEM1);
    cudaFuncSetAttribute(gemm_mma<2>, cudaFuncAttributeMaxDynamicSharedMemorySize, SMEM2);

    // merged fp32 -> fp16 split (single launch)
    split_all_kernel<<<(T3 + 255) / 256, 256>>>(u, W_dt, W_B, W_C);

    // dt GEMM (2-term, fp32+softplus out)
    gemm_mma<2><<<dim3(32, 4),   512, SMEM2>>>(b_dt, nullptr, dt_bias);
    // merged B+C GEMM (1-term, fp16 out)
    gemm_mma<1><<<dim3(32, 128), 512, SMEM1>>>(b_B,  b_C,     nullptr);

    // fused discretization + recurrent scan + skip
    scan_kernel<<<256, 128>>>(u, log_A, D_skip, y);
}

// round 10
// speedup vs baseline: 5.3792x; 1.0855x over previous
#include <cuda_runtime.h>
#include <cuda_fp16.h>
#include <math.h>
#include <stdint.h>

// Problem constants: B=2, L=2048, D=1024, N=16
#define M_ROWS 4096
#define K_DIM  1024
#define DN     16384

// ---------------------------------------------------------------------------
// Device scratch
// ---------------------------------------------------------------------------
__device__ __align__(256) __half g_u_h  [(size_t)M_ROWS * K_DIM];
__device__ __align__(256) __half g_Wdt_h[(size_t)1024  * K_DIM];
__device__ __align__(256) __half g_WB_h [(size_t)DN    * K_DIM];
__device__ __align__(256) __half g_WC_h [(size_t)DN    * K_DIM];
__device__ __align__(256) float  g_dt  [(size_t)M_ROWS * 1024];
__device__ __align__(256) __half g_Bt16[(size_t)M_ROWS * DN];
__device__ __align__(256) __half g_Ct16[(size_t)M_ROWS * DN];

// ---------------------------------------------------------------------------
// Helpers (family-portable PTX only)
// ---------------------------------------------------------------------------
__device__ __forceinline__ uint32_t smem_u32(const void* p) {
    uint32_t a;
    asm("{ .reg .u64 t; cvta.to.shared.u64 t, %1; cvt.u32.u64 %0, t; }"
        : "=r"(a) : "l"(p));
    return a;
}
__device__ __forceinline__ void cp16(uint32_t s, const void* g) {
    asm volatile("cp.async.cg.shared.global [%0], [%1], 16;" :: "r"(s), "l"(g));
}
#define CP_COMMIT() asm volatile("cp.async.commit_group;" ::: "memory")
#define CP_WAIT1()  asm volatile("cp.async.wait_group 1;"  ::: "memory")
#define CP_WAIT0()  asm volatile("cp.async.wait_group 0;"  ::: "memory")

__device__ __forceinline__ void ldsm4(uint32_t* r, uint32_t addr) {
    asm volatile("ldmatrix.sync.aligned.m8n8.x4.shared.b16 {%0,%1,%2,%3}, [%4];"
                 : "=r"(r[0]), "=r"(r[1]), "=r"(r[2]), "=r"(r[3]) : "r"(addr));
}
__device__ __forceinline__ void mma16816(float* d, const uint32_t* a, const uint32_t* b) {
    asm volatile(
        "mma.sync.aligned.m16n8k16.row.col.f32.f16.f16.f32 "
        "{%0,%1,%2,%3}, {%4,%5,%6,%7}, {%8,%9}, {%0,%1,%2,%3};"
        : "+f"(d[0]), "+f"(d[1]), "+f"(d[2]), "+f"(d[3])
        : "r"(a[0]), "r"(a[1]), "r"(a[2]), "r"(a[3]), "r"(b[0]), "r"(b[1]));
}

// ---------------------------------------------------------------------------
// Merged split kernel: fp32 -> fp16, all sources, one launch.
// Regions (float4 units): u | W_dt | W_B | W_C
// ---------------------------------------------------------------------------
#define U4    ((M_ROWS * K_DIM) / 4)          // 1048576
#define WDT4  ((1024 * K_DIM) / 4)            //  262144
#define WBC4  ((DN * K_DIM) / 4)              // 4194304
#define T0    (U4)
#define T1    (T0 + WDT4)
#define T2    (T1 + WBC4)
#define T3    (T2 + WBC4)

__global__ __launch_bounds__(256)
void split_all_kernel(const float* __restrict__ u,
                      const float* __restrict__ W_dt,
                      const float* __restrict__ W_B,
                      const float* __restrict__ W_C)
{
    int i = blockIdx.x * 256 + threadIdx.x;
    if (i >= T3) return;

    const float* src;
    __half* dst;
    int idx;
    if (i < T0)      { src = u;    dst = g_u_h;   idx = i; }
    else if (i < T1) { src = W_dt; dst = g_Wdt_h; idx = i - T0; }
    else if (i < T2) { src = W_B;  dst = g_WB_h;  idx = i - T1; }
    else             { src = W_C;  dst = g_WC_h;  idx = i - T2; }

    float4 x = ((const float4*)src)[idx];
    __half h[4];
    h[0] = __float2half_rn(x.x); h[1] = __float2half_rn(x.y);
    h[2] = __float2half_rn(x.z); h[3] = __float2half_rn(x.w);
    *((uint2*)(dst + 4 * (size_t)idx)) = *(uint2*)h;
}

// ---------------------------------------------------------------------------
// Unified fp16 mma.sync GEMM: out = u16 * W^T (+bias, +softplus for dt).
// 512 threads, 16 warps (2 m x 8 n), warp tile 64x32.
// Block 128x256, K-chunk 64, 3-stage cp.async, ONE barrier per chunk.
// grid = (32, 132): y<64 -> B (fp16 out), y<128 -> C (fp16 out),
//                   y>=128 -> dt (fp32 + softplus out, 4 slices of 256)
// ---------------------------------------------------------------------------
#define ROW_B     144                        // 128 data + 16 pad bytes
#define NSTAGE    3
#define A_BYTES   (128 * ROW_B)              // 18432
#define B_OFF     A_BYTES
#define STAGE_SZ  (A_BYTES + 256 * ROW_B)    // 55296
#define SMEM_GEMM (NSTAGE * STAGE_SZ)        // 165888

__global__ __launch_bounds__(512, 1)
void gemm_mma(const float* __restrict__ biasB,
              const float* __restrict__ biasC,
              const float* __restrict__ biasDt,
              const float* __restrict__ dtBias2)
{
    extern __shared__ char smem[];
    const uint32_t sb = smem_u32(smem);
    const int tid = threadIdx.x;
    const int wid = tid >> 5;             // 0..15
    const int lane = tid & 31;
    const int mBase = blockIdx.x * 128;
    const int warp_m = (wid >> 3) * 64;   // 0 or 64
    const int warp_n = (wid & 7) * 32;    // 0..224

    const int byg = blockIdx.y;           // 0..131
    const bool isDt = byg >= 128;
    const bool isC  = (byg >= 64) && !isDt;
    const __half* W = isDt ? g_Wdt_h : (isC ? g_WC_h : g_WB_h);
    const float* bias1 = isDt ? biasDt : (isC ? biasC : biasB);
    __half* out16 = isC ? g_Ct16 : g_Bt16;
    const int nBase = isDt ? (byg - 128) * 256 : (byg & 63) * 256;

    auto load_stage = [&](int s, int k0) {
        const uint32_t st = sb + (uint32_t)s * STAGE_SZ;
        #pragma unroll
        for (int i = 0; i < 2; i++) {     // A: 128 rows x 128B = 1024 cp16
            int idx = i * 512 + tid;
            int row = idx >> 3, c = idx & 7;
            uint32_t so = (uint32_t)(row * ROW_B + c * 16);
            size_t go = (size_t)(mBase + row) * K_DIM + k0 + c * 8;
            cp16(st + so, g_u_h + go);
        }
        #pragma unroll
        for (int i = 0; i < 4; i++) {     // B: 256 rows x 128B = 2048 cp16
            int idx = i * 512 + tid;
            int row = idx >> 3, c = idx & 7;
            uint32_t so = (uint32_t)(row * ROW_B + c * 16);
            size_t go = (size_t)(nBase + row) * K_DIM + k0 + c * 8;
            cp16(st + B_OFF + so, W + go);
        }
    };

    float acc[4][4][4];
    #pragma unroll
    for (int i = 0; i < 4; i++)
        #pragma unroll
        for (int j = 0; j < 4; j++)
            #pragma unroll
            for (int q = 0; q < 4; q++)
                acc[i][j][q] = 0.0f;

    const int aRow  = lane & 15;
    const int aHalf = lane >> 4;
    const int bJ    = lane & 7;
    const int bG    = lane >> 3;
    const int bRow  = (bG >> 1) * 8 + bJ;
    const int bHalf = bG & 1;

    load_stage(0, 0);   CP_COMMIT();
    load_stage(1, 64);  CP_COMMIT();

    const int NCHUNK = K_DIM / 64;        // 16
    for (int c = 0; c < NCHUNK; c++) {
        CP_WAIT1();                       // oldest group (chunk c) complete
        __syncthreads();

        if (c + 2 < NCHUNK) load_stage((c + 2) % NSTAGE, (c + 2) * 64);
        CP_COMMIT();

        const uint32_t st = sb + (uint32_t)(c % NSTAGE) * STAGE_SZ;
        #pragma unroll
        for (int ks = 0; ks < 4; ks++) {
            const uint32_t kOff = ks * 32;          // 16 halves = 32B
            uint32_t ah[4][4], bh[4][2];
            #pragma unroll
            for (int i = 0; i < 4; i++) {
                uint32_t ao = (uint32_t)((warp_m + i * 16 + aRow) * ROW_B)
                              + kOff + aHalf * 16;
                ldsm4(ah[i], st + ao);
            }
            #pragma unroll
            for (int j = 0; j < 2; j++) {
                uint32_t bo = (uint32_t)((warp_n + j * 16 + bRow) * ROW_B)
                              + kOff + bHalf * 16;
                uint32_t rh[4];
                ldsm4(rh, st + B_OFF + bo);
                bh[2*j][0] = rh[0]; bh[2*j][1] = rh[1];
                bh[2*j+1][0] = rh[2]; bh[2*j+1][1] = rh[3];
            }
            #pragma unroll
            for (int i = 0; i < 4; i++)
                #pragma unroll
                for (int j = 0; j < 4; j++)
                    mma16816(acc[i][j], ah[i], bh[j]);
        }
    }
    CP_WAIT0();

    // ---- epilogue: each warp writes its 64x32 tile
    const int r0 = (lane >> 2);
    const int c0 = (lane & 3) * 2;
    #pragma unroll
    for (int i = 0; i < 4; i++) {
        const int gr0 = mBase + warp_m + i * 16 + r0;
        #pragma unroll
        for (int j = 0; j < 4; j++) {
            const int gc = nBase + warp_n + j * 8 + c0;
            float v0 = acc[i][j][0] + bias1[gc];
            float v1 = acc[i][j][1] + bias1[gc + 1];
            float v2 = acc[i][j][2] + bias1[gc];
            float v3 = acc[i][j][3] + bias1[gc + 1];
            if (isDt) {
                v0 += dtBias2[gc];     v1 += dtBias2[gc + 1];
                v2 += dtBias2[gc];     v3 += dtBias2[gc + 1];
                v0 = fmaxf(v0, 0.0f) + log1pf(__expf(-fabsf(v0)));
                v1 = fmaxf(v1, 0.0f) + log1pf(__expf(-fabsf(v1)));
                v2 = fmaxf(v2, 0.0f) + log1pf(__expf(-fabsf(v2)));
                v3 = fmaxf(v3, 0.0f) + log1pf(__expf(-fabsf(v3)));
                *(float2*)(g_dt + (size_t)gr0       * 1024 + gc) = make_float2(v0, v1);
                *(float2*)(g_dt + (size_t)(gr0 + 8) * 1024 + gc) = make_float2(v2, v3);
            } else {
                *(__half2*)(out16 + (size_t)gr0       * DN + gc) = __floats2half2_rn(v0, v1);
                *(__half2*)(out16 + (size_t)(gr0 + 8) * DN + gc) = __floats2half2_rn(v2, v3);
            }
        }
    }
}

// ---------------------------------------------------------------------------
// Scan: one thread per (b, d, n). Block = 8 d x 16 n = 128 thr. Grid = 256.
// ---------------------------------------------------------------------------
__global__ __launch_bounds__(128)
void scan_kernel(const float* __restrict__ u,
                 const float* __restrict__ logA,
                 const float* __restrict__ Dskip,
                 float* __restrict__ y)
{
    const int tid  = threadIdx.x;
    const int n    = tid & 15;
    const int dl   = tid >> 4;
    const int blk  = blockIdx.x;
    const int b    = blk >> 7;
    const int dblk = blk & 127;
    const int d    = dblk * 8 + dl;

    const float Aval = -__expf(logA[d * 16 + n]);
    const float invA = 1.0f / Aval;
    const float dsk  = Dskip[d];

    const float*  uB  = u      + (size_t)b * 2048 * 1024;
    const float*  dtB = g_dt   + (size_t)b * 2048 * 1024;
    const __half* BtB = g_Bt16 + (size_t)b * 2048 * DN;
    const __half* CtB = g_Ct16 + (size_t)b * 2048 * DN;
    float*        yB  = y      + (size_t)b * 2048 * 1024;

    const int off = dblk * 128 + tid;

    float h = 0.0f;
    #pragma unroll 2
    for (int t = 0; t < 2048; ++t) {
        const float uv  = uB [t * 1024 + d];
        const float dtv = dtB[t * 1024 + d];
        const float Btv = __half2float(BtB[(size_t)t * DN + off]);
        const float Ctv = __half2float(CtB[(size_t)t * DN + off]);

        const float a = __expf(dtv * Aval);
        const float x = (a - 1.0f) * invA * Btv * uv;
        h = fmaf(a, h, x);

        float p = Ctv * h;
        p += __shfl_down_sync(0xffffffffu, p, 8, 16);
        p += __shfl_down_sync(0xffffffffu, p, 4, 16);
        p += __shfl_down_sync(0xffffffffu, p, 2, 16);
        p += __shfl_down_sync(0xffffffffu, p, 1, 16);

        if (n == 0)
            yB[t * 1024 + d] = p + dsk * uv;
    }
}

// ---------------------------------------------------------------------------
extern "C" void kernel_launch(void* const* d_in, const int* in_sizes, int n_in,
                              void* d_out, int out_size)
{
    const float* u       = (const float*)d_in[0];
    const float* log_A   = (const float*)d_in[1];
    const float* D_skip  = (const float*)d_in[2];
    const float* dt_bias = (const float*)d_in[3];
    const float* W_dt    = (const float*)d_in[4];
    const float* b_dt    = (const float*)d_in[5];
    const float* W_B     = (const float*)d_in[6];
    const float* b_B     = (const float*)d_in[7];
    const float* W_C     = (const float*)d_in[8];
    const float* b_C     = (const float*)d_in[9];
    float* y = (float*)d_out;

    cudaFuncSetAttribute(gemm_mma, cudaFuncAttributeMaxDynamicSharedMemorySize, SMEM_GEMM);

    // merged fp32 -> fp16 split (single launch)
    split_all_kernel<<<(T3 + 255) / 256, 256>>>(u, W_dt, W_B, W_C);

    // single unified GEMM launch: B (y<64), C (y<128), dt (y>=128)
    gemm_mma<<<dim3(32, 132), 512, SMEM_GEMM>>>(b_B, b_C, b_dt, dt_bias);

    // fused discretization + recurrent scan + skip
    scan_kernel<<<256, 128>>>(u, log_A, D_skip, y);
}